// round 4
// baseline (speedup 1.0000x reference)
#include <cuda_runtime.h>
#include <math.h>

#define E 64
#define CHUNK 32                 // tokens per routing chunk
#define MAX_TOK 16384
#define MAX_CHUNKS (MAX_TOK / CHUNK)

// Scratch (no allocations allowed)
__device__ int   g_idx[MAX_TOK];      // per-token argmax expert
__device__ float g_gate[MAX_TOK];     // per-token softmax prob at argmax
__device__ int   g_slot[MAX_TOK];     // per-token flat slot e*cap+r, or -1
__device__ int   g_hist[MAX_CHUNKS * E];

// ---------------------------------------------------------------------------
// Kernel 1: per-token argmax + softmax prob + per-chunk histogram.
// 32 tokens/block, 4 threads/token (16 experts each) -> 128 threads,
// grid = ceil(s/32) = 256 for s=8192: full chip coverage.
// ---------------------------------------------------------------------------
__global__ void route_kernel(const float* __restrict__ in, int s) {
    __shared__ int hist[E];

    int blk     = blockIdx.x;
    int tid     = threadIdx.x;        // 0..127
    int t_local = tid >> 2;           // token within chunk 0..31
    int part    = tid & 3;            // 16-expert slice
    int token   = blk * CHUNK + t_local;
    bool valid  = (token < s);
    int  tok_c  = valid ? token : (s - 1);

    if (tid < E) hist[tid] = 0;

    const float4* p4 = (const float4*)(in + (size_t)tok_c * E + part * 16);
    float4 a = p4[0], b = p4[1], c = p4[2], d = p4[3];
    float v[16] = {a.x, a.y, a.z, a.w, b.x, b.y, b.z, b.w,
                   c.x, c.y, c.z, c.w, d.x, d.y, d.z, d.w};

    float m = v[0];
    int   am = part * 16;
#pragma unroll
    for (int k = 1; k < 16; k++)
        if (v[k] > m) { m = v[k]; am = part * 16 + k; }
#pragma unroll
    for (int off = 1; off < 4; off <<= 1) {
        float mo = __shfl_xor_sync(0xffffffffu, m, off);
        int   ao = __shfl_xor_sync(0xffffffffu, am, off);
        if (mo > m || (mo == m && ao < am)) { m = mo; am = ao; }
    }
    float sum = 0.f;
#pragma unroll
    for (int k = 0; k < 16; k++) sum += __expf(v[k] - m);
#pragma unroll
    for (int off = 1; off < 4; off <<= 1)
        sum += __shfl_xor_sync(0xffffffffu, sum, off);

    __syncthreads();
    if (valid && part == 0) {
        g_idx[token]  = am;
        g_gate[token] = 1.0f / sum;
        atomicAdd(&hist[am], 1);
    }
    __syncthreads();
    if (tid < E) g_hist[blk * E + tid] = hist[tid];
}

// ---------------------------------------------------------------------------
// Kernel 2: fused cross-chunk exclusive prefix + per-token slot.
// 64 threads/block, 32 tokens/block. Loads only the PRECEDING chunks'
// histograms into dynamic smem; in-chunk rank via single-warp match_any.
// ---------------------------------------------------------------------------
__global__ void prefix_slot_kernel(int s, int cap) {
    extern __shared__ int hist_sh[];          // blk * E ints
    __shared__ int base_sh[E];
    __shared__ int idx_sh[CHUNK];

    int blk = blockIdx.x;
    int tid = threadIdx.x;                    // 0..63

    int need = blk * E;
    for (int i = tid; i < need; i += 64) hist_sh[i] = g_hist[i];

    int base = blk * CHUNK;
    int tokens = s - base;
    if (tokens > CHUNK) tokens = CHUNK;
    if (tid < tokens) idx_sh[tid] = g_idx[base + tid];
    __syncthreads();

    if (tid < E) {
        int r = 0;
        for (int c = 0; c < blk; c++) r += hist_sh[c * E + tid];
        base_sh[tid] = r;
    }
    __syncthreads();

    if (tid < 32) {
        int e = (tid < tokens) ? idx_sh[tid] : -1;
        unsigned mask = __match_any_sync(0xffffffffu, e);
        int within = __popc(mask & ((1u << tid) - 1));
        if (tid < tokens) {
            int r = base_sh[e] + within;
            g_slot[base + tid] = (r < cap) ? (e * cap + r) : -1;
        }
    }
}

// ---------------------------------------------------------------------------
// Kernel 3: fill. One block per (token, tensor): blocks [0,s) write the
// combine tensor, [s,2s) the mask tensor. Pure contiguous streaming zero
// stores, then one scalar fix-up per block.
// ---------------------------------------------------------------------------
__global__ void fill_kernel(float* __restrict__ out, size_t sec, int row,
                            int s) {
    int b = blockIdx.x;
    bool is_mask = (b >= s);
    int t = is_mask ? b - s : b;

    float* __restrict__ base = out + (is_mask ? sec : 0) + (size_t)t * row;
    float4* __restrict__ d4 = (float4*)base;
    int n4 = row >> 2;
    float4 z = make_float4(0.f, 0.f, 0.f, 0.f);

    for (int i = threadIdx.x; i < n4; i += blockDim.x)
        __stcs(&d4[i], z);
    __syncthreads();

    if (threadIdx.x == 0) {
        int p = g_slot[t];
        if (p >= 0) base[p] = is_mask ? 1.0f : g_gate[t];
    }
}

// ---------------------------------------------------------------------------
// Kernel 4: zero any tail beyond the two tensors (output poisoned 0xAA)
// ---------------------------------------------------------------------------
__global__ void tail_zero(float* __restrict__ out, size_t start, size_t end) {
    size_t i = start + blockIdx.x * (size_t)blockDim.x + threadIdx.x;
    size_t stride = gridDim.x * (size_t)blockDim.x;
    for (; i < end; i += stride) out[i] = 0.f;
}

// ---------------------------------------------------------------------------
extern "C" void kernel_launch(void* const* d_in, const int* in_sizes, int n_in,
                              void* d_out, int out_size) {
    const float* in = (const float*)d_in[0];
    float* out = (float*)d_out;

    int total = in_sizes[0];
    int s = total / E;
    int cap = (int)floor(1.25 * (double)s / (double)E);
    cap += (cap & 1);
    if (cap < 4) cap = 4;

    int row = E * cap;
    size_t sec = (size_t)s * (size_t)row;
    int write_mask = ((size_t)out_size >= 2 * sec) ? 1 : 0;

    int nchunks = (s + CHUNK - 1) / CHUNK;

    // 1) router
    route_kernel<<<nchunks, 128>>>(in, s);

    // 2) fused prefix + slot (dynamic smem = preceding-chunk hist table)
    size_t smem_bytes = (size_t)nchunks * E * sizeof(int);
    if (smem_bytes > 48 * 1024) {
        cudaFuncSetAttribute(prefix_slot_kernel,
                             cudaFuncAttributeMaxDynamicSharedMemorySize,
                             (int)smem_bytes);
    }
    prefix_slot_kernel<<<nchunks, 64, smem_bytes>>>(s, cap);

    // 3) streaming fill + fix-up (combine blocks then mask blocks)
    int grid = write_mask ? 2 * s : s;
    fill_kernel<<<grid, 256>>>(out, sec, row, s);

    // 4) tail beyond 2*sec, if any
    size_t covered = write_mask ? 2 * sec : sec;
    if ((size_t)out_size > covered) {
        tail_zero<<<256, 256>>>(out, covered, (size_t)out_size);
    }
}